// round 13
// baseline (speedup 1.0000x reference)
#include <cuda_runtime.h>

#define R    5
#define E    50000
#define NUU  20000
#define NII  20000
#define NF   4
#define DN   16
#define DR   64
#define DOUT 64
#define TILE_E 128

// ---------------- scratch (allocation-free: __device__ globals) ----------------
__device__ float4 g_hu[R*NUU*4];     // hu[r,n,0:16]
__device__ float4 g_hi[R*NII*4];
__device__ float  g_blend[R*E];
__device__ float  g_norm_u[NUU];
__device__ float  g_norm_i[NII];
__device__ float4 g_umsg[NUU*4];
__device__ float4 g_imsg[NII*4];

__device__ __forceinline__ float dot4(float4 a, float4 b){
    return a.x*b.x + a.y*b.y + a.z*b.z + a.w*b.w;
}

__device__ __forceinline__ void red_add_v4(float4* addr, float4 v){
    asm volatile("red.global.add.v4.f32 [%0], {%1,%2,%3,%4};"
                 :: "l"(addr), "f"(v.x), "f"(v.y), "f"(v.z), "f"(v.w)
                 : "memory");
}

// packed fp32x2 helpers (sm_103a; ptxas never auto-emits FFMA2)
__device__ __forceinline__ void ffma2(unsigned long long &d,
                                      unsigned long long a, unsigned long long b){
    asm("fma.rn.f32x2 %0, %1, %2, %0;" : "+l"(d) : "l"(a), "l"(b));
}
__device__ __forceinline__ float hsum2(unsigned long long v){
    float lo, hi;
    asm("mov.b64 {%0, %1}, %2;" : "=f"(lo), "=f"(hi) : "l"(v));
    return lo + hi;
}

// ---------------- K0: zero accumulators ----------------
__global__ void __launch_bounds__(256) k_zero(){
    int i = blockIdx.x*256 + threadIdx.x;
    if (i < NUU) g_norm_u[i] = 0.f;
    if (i < NII) g_norm_i[i] = 0.f;
    float4 z = make_float4(0.f,0.f,0.f,0.f);
    if (i < NUU*4) g_umsg[i] = z;
    if (i < NII*4) g_imsg[i] = z;
}

// ---------------- K1: hu/hi = node_h[k] @ node_w^T ----------------
__global__ void __launch_bounds__(256) k_nodes(
    const float* __restrict__ user_h, const float* __restrict__ item_h,
    const float* __restrict__ w_fwd,  const float* __restrict__ w_rev,
    const int*   __restrict__ kp)
{
    __shared__ float Ws[DN*DN];
    int r = blockIdx.y, side = blockIdx.z;
    const float* W = side ? w_rev : w_fwd;
    Ws[threadIdx.x] = W[r*DN*DN + threadIdx.x];
    __syncthreads();
    int n = blockIdx.x*256 + threadIdx.x;
    if (n >= NUU) return;
    int kv = __ldg(kp);
    const float* hp = (side ? item_h : user_h) + ((size_t)(kv*R + r)*NUU + n)*DN;
    const float4* h4 = (const float4*)hp;
    float h[16];
    #pragma unroll
    for (int j=0;j<4;j++){
        float4 v = h4[j];
        h[4*j]=v.x; h[4*j+1]=v.y; h[4*j+2]=v.z; h[4*j+3]=v.w;
    }
    float4* out = (side ? g_hi : g_hu) + ((size_t)r*NUU + n)*4;
    #pragma unroll
    for (int q=0;q<4;q++){
        float acc[4];
        #pragma unroll
        for (int t=0;t<4;t++){
            int o = q*4+t;
            float a = 0.f;
            #pragma unroll
            for (int d=0; d<16; d++) a += h[d]*Ws[o*16+d];
            acc[t] = a;
        }
        out[q] = make_float4(acc[0],acc[1],acc[2],acc[3]);
    }
}

// ---------------- K2: blended weights, warp-cooperative (8 lanes / edge) ----------
__global__ void __launch_bounds__(256) k_blend(
    const float* __restrict__ user_h,    const float* __restrict__ item_h,
    const float* __restrict__ user_hsum, const float* __restrict__ item_hsum,
    const float* __restrict__ review_feat, const float* __restrict__ prototypes,
    const float* __restrict__ eta,
    const int*   __restrict__ edge_src,  const int* __restrict__ edge_dst,
    const int*   __restrict__ kp)
{
    __shared__ float4 Pr[NF*DR/4];   // 64 float4
    int r   = blockIdx.y;
    int tid = threadIdx.x;
    if (tid < NF*DR/4) Pr[tid] = ((const float4*)prototypes)[tid];
    __syncthreads();

    int g = tid >> 3;        // group (edge) within block: 0..31
    int l = tid & 7;         // lane within group
    int e = blockIdx.x*32 + g;
    bool valid = (e < E);
    int ec  = valid ? e : (E-1);      // clamp so shfl groups stay converged
    int idx = r*E + ec;
    int kv  = __ldg(kp);
    int src = __ldg(edge_src + idx);
    int dst = __ldg(edge_dst + idx);

    // ---- sim_k: cosine of user_h[k][r][src] vs item_h[k][r][dst] ----
    float uu=0.f, ii=0.f, ui=0.f;
    if (l < 4){
        float4 a = __ldg((const float4*)(user_h + ((size_t)(kv*R + r)*NUU + src)*DN) + l);
        float4 b = __ldg((const float4*)(item_h + ((size_t)(kv*R + r)*NII + dst)*DN) + l);
        uu = dot4(a,a); ii = dot4(b,b); ui = dot4(a,b);
    }
    #pragma unroll
    for (int s=1; s<8; s<<=1){
        uu += __shfl_xor_sync(0xffffffffu, uu, s, 8);
        ii += __shfl_xor_sync(0xffffffffu, ii, s, 8);
        ui += __shfl_xor_sync(0xffffffffu, ui, s, 8);
    }

    // ---- sim_all denominator: lane pair (2f,2f+1) handles factor f ----
    const float4* ru = (const float4*)(user_hsum + ((size_t)(r*NUU+src))*NF*DN);
    const float4* ci = (const float4*)(item_hsum + ((size_t)(r*NII+dst))*NF*DN);
    int off = (l>>1)*4 + (l&1)*2;
    float p = dot4(__ldg(ru+off),   __ldg(ci+off))
            + dot4(__ldg(ru+off+1), __ldg(ci+off+1));
    p += __shfl_xor_sync(0xffffffffu, p, 1, 8);     // full dot_f on both pair lanes
    float es = __expf(2.0f*p) * 0.5f;               // halve: each f counted twice
    es += __shfl_xor_sync(0xffffffffu, es, 1, 8);
    es += __shfl_xor_sync(0xffffffffu, es, 2, 8);
    es += __shfl_xor_sync(0xffffffffu, es, 4, 8);   // es = sum_f exp(sim_all_f)

    // ---- anchors: lane l covers float4s {2l, 2l+1} of each factor ----
    const float4* rf = (const float4*)(review_feat + (size_t)idx*NF*DR);
    float pa[NF];
    #pragma unroll
    for (int f=0; f<NF; f++){
        int o = f*16 + l*2;
        pa[f] = dot4(__ldg(rf+o),   Pr[o])
              + dot4(__ldg(rf+o+1), Pr[o+1]);
    }
    #pragma unroll
    for (int f=0; f<NF; f++){
        #pragma unroll
        for (int s=1; s<8; s<<=1)
            pa[f] += __shfl_xor_sync(0xffffffffu, pa[f], s, 8);
    }
    float dA = 0.f, aK = 0.f;
    #pragma unroll
    for (int f=0; f<NF; f++){
        float af = 2.0f*pa[f];
        dA += __expf(af);
        if (f == kv) aK = af;
    }

    if (l == 0 && valid){
        float den = fmaxf(sqrtf(uu),1e-12f) * fmaxf(sqrtf(ii),1e-12f);
        float sim_k = (ui/den) * 2.0f;
        float exp_sim    = __expf(sim_k)/es;
        float exp_anchor = __expf(aK)/dA;
        float et = __ldg(eta + idx);
        float gg = 1.0f/(1.0f + __expf(-et));
        float blended = gg*exp_anchor + (1.0f-gg)*exp_sim;
        g_blend[idx] = blended;
        atomicAdd(&g_norm_u[src], blended);
        atomicAdd(&g_norm_i[dst], blended);
    }
}

// ---------------- K3: GEMM tile, k-packed FFMA2 (R10 shape) + scatter ----------
// 256 threads = 64 edge-cols x 4 output-groups; thread C-tile = 2 edges x 8 outs.
// FFMA2 halves hold even/odd-k partials: A operand comes straight from the float4
// tile (zero packing MOVs); weights stay k-major (natural gmem layout).
// og = tid>>6 -> whole warp shares og -> W-LDS are warp-uniform broadcasts.
__global__ void __launch_bounds__(256) k_msg(
    const float* __restrict__ review_feat,
    const float* __restrict__ rw_fwd, const float* __restrict__ rw_rev,
    const int*   __restrict__ edge_src, const int* __restrict__ edge_dst,
    const int*   __restrict__ kp, float* __restrict__ out)
{
    __shared__ float4 A4[TILE_E*17];      // 34816 B, row pad 17 (conflict-free)
    __shared__ float  Wt[2*DN*DR];        //  8192 B: rows 0-15 fwd, 16-31 rev (k-major)
    int r   = blockIdx.y;
    int tid = threadIdx.x;
    int kv  = __ldg(kp);
    int Eb  = blockIdx.x*TILE_E;

    for (int i = tid; i < 2*DN*DR; i += 256)
        Wt[i] = (i < DN*DR) ? rw_fwd[(size_t)r*DN*DR + i]
                            : rw_rev[(size_t)r*DN*DR + i - DN*DR];
    for (int i = tid; i < TILE_E*16; i += 256){
        int row = i >> 4, col = i & 15;
        int er = Eb + row; if (er >= E) er = E-1;
        A4[row*17 + col] =
            __ldg((const float4*)(review_feat + ((size_t)(r*E+er)*NF + kv)*DR) + col);
    }
    __syncthreads();

    int og = tid >> 6;          // 0..3 : warp-uniform (og0/1 = fwd o0-7/8-15, og2/3 = rev)
    int eg = tid & 63;          // 0..63: edge column
    const ulonglong2* a0 = (const ulonglong2*)&A4[eg*17];
    const ulonglong2* a1 = (const ulonglong2*)&A4[(64+eg)*17];
    const ulonglong2* Wb = (const ulonglong2*)(Wt + og*8*DR);   // 8 rows of 64 floats

    unsigned long long c0[8], c1[8];
    #pragma unroll
    for (int o=0;o<8;o++){ c0[o]=0ull; c1[o]=0ull; }

    #pragma unroll 8
    for (int kq=0; kq<16; kq++){
        ulonglong2 x0 = a0[kq];             // (k0,k1),(k2,k3) of edge eg
        ulonglong2 x1 = a1[kq];             // same k-chunk of edge 64+eg
        #pragma unroll
        for (int o=0;o<8;o++){
            ulonglong2 w = Wb[o*16 + kq];   // broadcast LDS.128 (warp-uniform)
            ffma2(c0[o], x0.x, w.x);  ffma2(c0[o], x0.y, w.y);
            ffma2(c1[o], x1.x, w.x);  ffma2(c1[o], x1.y, w.y);
        }
    }

    // ---- epilogue: each thread scatters its 8-float slice for its 2 edges ----
    int oBase = (og & 1)*8;                 // float offset within 16-dim vector
    bool fwd  = (og < 2);
    #pragma unroll
    for (int ei=0; ei<2; ei++){
        int e = Eb + 64*ei + eg;
        if (e >= E) continue;
        int idx = r*E + e;
        int src = __ldg(edge_src + idx);
        int dst = __ldg(edge_dst + idx);
        float b = g_blend[idx];
        float w = b * rsqrtf(g_norm_u[src]*g_norm_i[dst]);
        if (og == 0) out[NUU*DOUT + NII*DOUT + idx] = w;   // int_dist once

        const unsigned long long* cc = ei ? c1 : c0;
        float o8[8];
        #pragma unroll
        for (int o=0;o<8;o++) o8[o] = hsum2(cc[o]);

        if (fwd){
            const float4* hu = (const float4*)((const float*)g_hu
                               + ((size_t)r*NUU + src)*DN + oBase);
            float4 h0 = __ldg(hu), h1 = __ldg(hu+1);
            float4* t = (float4*)((float*)g_imsg + (size_t)dst*DN + oBase);
            red_add_v4(t,   make_float4((h0.x+o8[0])*w,(h0.y+o8[1])*w,
                                        (h0.z+o8[2])*w,(h0.w+o8[3])*w));
            red_add_v4(t+1, make_float4((h1.x+o8[4])*w,(h1.y+o8[5])*w,
                                        (h1.z+o8[6])*w,(h1.w+o8[7])*w));
        } else {
            const float4* hi = (const float4*)((const float*)g_hi
                               + ((size_t)r*NII + dst)*DN + oBase);
            float4 h0 = __ldg(hi), h1 = __ldg(hi+1);
            float4* t = (float4*)((float*)g_umsg + (size_t)src*DN + oBase);
            red_add_v4(t,   make_float4((h0.x+o8[0])*w,(h0.y+o8[1])*w,
                                        (h0.z+o8[2])*w,(h0.w+o8[3])*w));
            red_add_v4(t+1, make_float4((h1.x+o8[4])*w,(h1.y+o8[5])*w,
                                        (h1.z+o8[6])*w,(h1.w+o8[7])*w));
        }
    }
}

// ---------------- K4: leaky_relu + FC epilogue (4 outputs/thread, v4 store) ----
__global__ void __launch_bounds__(256) k_fc(
    const float* __restrict__ ufc_w, const float* __restrict__ ufc_b,
    const float* __restrict__ ifc_w, const float* __restrict__ ifc_b,
    float* __restrict__ out)
{
    __shared__ float Ws[DN*DOUT];   // transposed: Ws[j*64+o] = W[o*16+j]
    __shared__ float Bs[DOUT];
    int side = blockIdx.y;
    const float* W = side ? ifc_w : ufc_w;
    const float* B = side ? ifc_b : ufc_b;
    for (int i = threadIdx.x; i < DN*DOUT; i += 256){
        int o = i >> 4, j = i & 15;         // coalesced gmem read of W
        Ws[j*DOUT + o] = W[i];
    }
    if (threadIdx.x < DOUT) Bs[threadIdx.x] = B[threadIdx.x];
    __syncthreads();

    int idx = blockIdx.x*256 + threadIdx.x;   // < NUU*DOUT/4
    int n  = idx >> 4;
    int o4 = (idx & 15)*4;
    const float4* msg4 = (const float4*)((const float*)(side ? g_imsg : g_umsg) + (size_t)n*DN);
    float4 acc = *(const float4*)(Bs + o4);
    #pragma unroll
    for (int q=0;q<4;q++){
        float4 m = msg4[q];                  // warp-broadcast
        float xs[4] = {(m.x>0.f)?m.x:0.1f*m.x, (m.y>0.f)?m.y:0.1f*m.y,
                       (m.z>0.f)?m.z:0.1f*m.z, (m.w>0.f)?m.w:0.1f*m.w};
        #pragma unroll
        for (int t=0;t<4;t++){
            const float4 wv = *(const float4*)(Ws + (4*q+t)*DOUT + o4);
            acc.x += xs[t]*wv.x;  acc.y += xs[t]*wv.y;
            acc.z += xs[t]*wv.z;  acc.w += xs[t]*wv.w;
        }
    }
    *(float4*)(out + (size_t)side*NUU*DOUT + (size_t)n*DOUT + o4) = acc;
}

// ---------------- launch ----------------
extern "C" void kernel_launch(void* const* d_in, const int* in_sizes, int n_in,
                              void* d_out, int out_size)
{
    const float* user_h      = (const float*)d_in[0];
    const float* item_h      = (const float*)d_in[1];
    const float* user_hsum   = (const float*)d_in[2];
    const float* item_hsum   = (const float*)d_in[3];
    const float* review_feat = (const float*)d_in[4];
    const float* prototypes  = (const float*)d_in[5];
    const float* eta         = (const float*)d_in[6];
    const float* node_w_fwd  = (const float*)d_in[7];
    const float* review_w_fwd= (const float*)d_in[8];
    const float* node_w_rev  = (const float*)d_in[9];
    const float* review_w_rev= (const float*)d_in[10];
    const float* ufc_w       = (const float*)d_in[11];
    const float* ufc_b       = (const float*)d_in[12];
    const float* ifc_w       = (const float*)d_in[13];
    const float* ifc_b       = (const float*)d_in[14];
    const int*   edge_src    = (const int*)d_in[15];
    const int*   edge_dst    = (const int*)d_in[16];
    const int*   kp          = (const int*)d_in[17];
    float* out = (float*)d_out;

    k_zero <<<(NUU*4 + 255)/256, 256>>>();
    k_nodes<<<dim3((NUU+255)/256, R, 2), 256>>>(user_h, item_h, node_w_fwd, node_w_rev, kp);
    k_blend<<<dim3((E+31)/32, R), 256>>>(user_h, item_h, user_hsum, item_hsum,
                                         review_feat, prototypes, eta,
                                         edge_src, edge_dst, kp);
    k_msg  <<<dim3((E+TILE_E-1)/TILE_E, R), 256>>>(review_feat, review_w_fwd, review_w_rev,
                                                   edge_src, edge_dst, kp, out);
    k_fc   <<<dim3((NUU*DOUT/4)/256, 2), 256>>>(ufc_w, ufc_b, ifc_w, ifc_b, out);
}

// round 14
// speedup vs baseline: 1.1011x; 1.1011x over previous
#include <cuda_runtime.h>

#define R    5
#define E    50000
#define NUU  20000
#define NII  20000
#define NF   4
#define DN   16
#define DR   64
#define DOUT 64
#define TILE_E 128

// ---------------- scratch (allocation-free: __device__ globals) ----------------
__device__ float4 g_hu[R*NUU*4];     // hu[r,n,0:16]
__device__ float4 g_hi[R*NII*4];
__device__ float  g_blend[R*E];
__device__ float  g_norm_u[NUU];
__device__ float  g_norm_i[NII];
__device__ float4 g_umsg[NUU*4];
__device__ float4 g_imsg[NII*4];

__device__ __forceinline__ float dot4(float4 a, float4 b){
    return a.x*b.x + a.y*b.y + a.z*b.z + a.w*b.w;
}

__device__ __forceinline__ void red_add_v4(float4* addr, float4 v){
    asm volatile("red.global.add.v4.f32 [%0], {%1,%2,%3,%4};"
                 :: "l"(addr), "f"(v.x), "f"(v.y), "f"(v.z), "f"(v.w)
                 : "memory");
}

// packed fp32x2 helpers (sm_103a; ptxas never auto-emits FFMA2)
__device__ __forceinline__ unsigned long long pk2(float x){
    unsigned long long r;
    asm("mov.b64 %0, {%1, %1};" : "=l"(r) : "f"(x));
    return r;
}
__device__ __forceinline__ void ffma2(unsigned long long &d,
                                      unsigned long long a, unsigned long long b){
    asm("fma.rn.f32x2 %0, %1, %2, %0;" : "+l"(d) : "l"(a), "l"(b));
}
__device__ __forceinline__ void unpk2(unsigned long long v, float &lo, float &hi){
    asm("mov.b64 {%0, %1}, %2;" : "=f"(lo), "=f"(hi) : "l"(v));
}

// ---------------- K1: hu/hi = node_h[k] @ node_w^T  (+ folded zeroing) ---------
__global__ void __launch_bounds__(256) k_nodes(
    const float* __restrict__ user_h, const float* __restrict__ item_h,
    const float* __restrict__ w_fwd,  const float* __restrict__ w_rev,
    const int*   __restrict__ kp)
{
    // folded k_zero: flat id over the whole (x,y,z) grid covers all accumulators
    {
        int gid = ((blockIdx.z*R + blockIdx.y)*gridDim.x + blockIdx.x)*256 + threadIdx.x;
        float4 z = make_float4(0.f,0.f,0.f,0.f);
        if (gid < NUU*4) g_umsg[gid] = z;
        if (gid < NII*4) g_imsg[gid] = z;
        if (gid < NUU)   g_norm_u[gid] = 0.f;
        if (gid < NII)   g_norm_i[gid] = 0.f;
    }

    __shared__ float Ws[DN*DN];
    int r = blockIdx.y, side = blockIdx.z;
    const float* W = side ? w_rev : w_fwd;
    Ws[threadIdx.x] = W[r*DN*DN + threadIdx.x];
    __syncthreads();
    int n = blockIdx.x*256 + threadIdx.x;
    if (n >= NUU) return;
    int kv = __ldg(kp);
    const float* hp = (side ? item_h : user_h) + ((size_t)(kv*R + r)*NUU + n)*DN;
    const float4* h4 = (const float4*)hp;
    float h[16];
    #pragma unroll
    for (int j=0;j<4;j++){
        float4 v = h4[j];
        h[4*j]=v.x; h[4*j+1]=v.y; h[4*j+2]=v.z; h[4*j+3]=v.w;
    }
    float4* out = (side ? g_hi : g_hu) + ((size_t)r*NUU + n)*4;
    #pragma unroll
    for (int q=0;q<4;q++){
        float acc[4];
        #pragma unroll
        for (int t=0;t<4;t++){
            int o = q*4+t;
            float a = 0.f;
            #pragma unroll
            for (int d=0; d<16; d++) a += h[d]*Ws[o*16+d];
            acc[t] = a;
        }
        out[q] = make_float4(acc[0],acc[1],acc[2],acc[3]);
    }
}

// ---------------- K2: blended weights, warp-cooperative (8 lanes / edge) ----------
__global__ void __launch_bounds__(256) k_blend(
    const float* __restrict__ user_h,    const float* __restrict__ item_h,
    const float* __restrict__ user_hsum, const float* __restrict__ item_hsum,
    const float* __restrict__ review_feat, const float* __restrict__ prototypes,
    const float* __restrict__ eta,
    const int*   __restrict__ edge_src,  const int* __restrict__ edge_dst,
    const int*   __restrict__ kp)
{
    __shared__ float4 Pr[NF*DR/4];   // 64 float4
    int r   = blockIdx.y;
    int tid = threadIdx.x;
    if (tid < NF*DR/4) Pr[tid] = ((const float4*)prototypes)[tid];
    __syncthreads();

    int g = tid >> 3;        // group (edge) within block: 0..31
    int l = tid & 7;         // lane within group
    int e = blockIdx.x*32 + g;
    bool valid = (e < E);
    int ec  = valid ? e : (E-1);      // clamp so shfl groups stay converged
    int idx = r*E + ec;
    int kv  = __ldg(kp);
    int src = __ldg(edge_src + idx);
    int dst = __ldg(edge_dst + idx);

    // ---- sim_k: cosine of user_h[k][r][src] vs item_h[k][r][dst] ----
    float uu=0.f, ii=0.f, ui=0.f;
    if (l < 4){
        float4 a = __ldg((const float4*)(user_h + ((size_t)(kv*R + r)*NUU + src)*DN) + l);
        float4 b = __ldg((const float4*)(item_h + ((size_t)(kv*R + r)*NII + dst)*DN) + l);
        uu = dot4(a,a); ii = dot4(b,b); ui = dot4(a,b);
    }
    #pragma unroll
    for (int s=1; s<8; s<<=1){
        uu += __shfl_xor_sync(0xffffffffu, uu, s, 8);
        ii += __shfl_xor_sync(0xffffffffu, ii, s, 8);
        ui += __shfl_xor_sync(0xffffffffu, ui, s, 8);
    }

    // ---- sim_all denominator: lane pair (2f,2f+1) handles factor f ----
    const float4* ru = (const float4*)(user_hsum + ((size_t)(r*NUU+src))*NF*DN);
    const float4* ci = (const float4*)(item_hsum + ((size_t)(r*NII+dst))*NF*DN);
    int off = (l>>1)*4 + (l&1)*2;
    float p = dot4(__ldg(ru+off),   __ldg(ci+off))
            + dot4(__ldg(ru+off+1), __ldg(ci+off+1));
    p += __shfl_xor_sync(0xffffffffu, p, 1, 8);     // full dot_f on both pair lanes
    float es = __expf(2.0f*p) * 0.5f;               // halve: each f counted twice
    es += __shfl_xor_sync(0xffffffffu, es, 1, 8);
    es += __shfl_xor_sync(0xffffffffu, es, 2, 8);
    es += __shfl_xor_sync(0xffffffffu, es, 4, 8);   // es = sum_f exp(sim_all_f)

    // ---- anchors: lane l covers float4s {2l, 2l+1} of each factor ----
    const float4* rf = (const float4*)(review_feat + (size_t)idx*NF*DR);
    float pa[NF];
    #pragma unroll
    for (int f=0; f<NF; f++){
        int o = f*16 + l*2;
        pa[f] = dot4(__ldg(rf+o),   Pr[o])
              + dot4(__ldg(rf+o+1), Pr[o+1]);
    }
    #pragma unroll
    for (int f=0; f<NF; f++){
        #pragma unroll
        for (int s=1; s<8; s<<=1)
            pa[f] += __shfl_xor_sync(0xffffffffu, pa[f], s, 8);
    }
    float dA = 0.f, aK = 0.f;
    #pragma unroll
    for (int f=0; f<NF; f++){
        float af = 2.0f*pa[f];
        dA += __expf(af);
        if (f == kv) aK = af;
    }

    if (l == 0 && valid){
        float den = fmaxf(sqrtf(uu),1e-12f) * fmaxf(sqrtf(ii),1e-12f);
        float sim_k = (ui/den) * 2.0f;
        float exp_sim    = __expf(sim_k)/es;
        float exp_anchor = __expf(aK)/dA;
        float et = __ldg(eta + idx);
        float gg = 1.0f/(1.0f + __expf(-et));
        float blended = gg*exp_anchor + (1.0f-gg)*exp_sim;
        g_blend[idx] = blended;
        atomicAdd(&g_norm_u[src], blended);
        atomicAdd(&g_norm_i[dst], blended);
    }
}

// ---------------- K3: register-blocked GEMM tile + scatter (R12/R10 shape) -----
// 256 threads = 64 edge-cols x 4 output-groups; thread C-tile = 2 edges x 8 outs.
__global__ void __launch_bounds__(256) k_msg(
    const float* __restrict__ review_feat,
    const float* __restrict__ rw_fwd, const float* __restrict__ rw_rev,
    const int*   __restrict__ edge_src, const int* __restrict__ edge_dst,
    const int*   __restrict__ kp, float* __restrict__ out)
{
    __shared__ float4 A4[TILE_E*17];      // 34816 B
    __shared__ float  Wc[DR*36];          //  9216 B
    int r   = blockIdx.y;
    int tid = threadIdx.x;
    int kv  = __ldg(kp);
    int Eb  = blockIdx.x*TILE_E;

    // stage weights: Wc[d][o] fwd at o, rev at 16+o  (coalesced gmem reads)
    for (int i = tid; i < DN*DR; i += 256){
        int o = i >> 6, d = i & 63;
        Wc[d*36 + o]      = rw_fwd[(size_t)r*DN*DR + i];
        Wc[d*36 + 16 + o] = rw_rev[(size_t)r*DN*DR + i];
    }
    // stage A tile (rf_k rows), coalesced 64B+ chunks
    for (int i = tid; i < TILE_E*16; i += 256){
        int row = i >> 4, col = i & 15;
        int er = Eb + row; if (er >= E) er = E-1;
        A4[row*17 + col] =
            __ldg((const float4*)(review_feat + ((size_t)(r*E+er)*NF + kv)*DR) + col);
    }
    __syncthreads();

    int og = tid >> 6;          // 0..3 : output group (8 outputs)
    int eg = tid & 63;          // 0..63: edge column
    const float4* a0 = &A4[eg*17];
    const float4* a1 = &A4[(64+eg)*17];
    const float*  Wb = Wc + og*8;

    unsigned long long c0[4], c1[4];
    #pragma unroll
    for (int q=0;q<4;q++){ c0[q]=0ull; c1[q]=0ull; }

    #pragma unroll 4
    for (int kq=0; kq<16; kq++){
        float4 x0 = a0[kq];
        float4 x1 = a1[kq];
        float s0[4] = {x0.x,x0.y,x0.z,x0.w};
        float s1[4] = {x1.x,x1.y,x1.z,x1.w};
        #pragma unroll
        for (int c=0;c<4;c++){
            const ulonglong2* b2 = (const ulonglong2*)(Wb + (4*kq+c)*36);
            ulonglong2 bA = b2[0];              // outputs og*8+0..3 (broadcast)
            ulonglong2 bB = b2[1];              // outputs og*8+4..7
            unsigned long long p0 = pk2(s0[c]);
            unsigned long long p1 = pk2(s1[c]);
            ffma2(c0[0], p0, bA.x); ffma2(c0[1], p0, bA.y);
            ffma2(c0[2], p0, bB.x); ffma2(c0[3], p0, bB.y);
            ffma2(c1[0], p1, bA.x); ffma2(c1[1], p1, bA.y);
            ffma2(c1[2], p1, bB.x); ffma2(c1[3], p1, bB.y);
        }
    }

    // ---- epilogue: each thread scatters its 8-float slice for its 2 edges ----
    int oBase = (og & 1)*8;                 // float offset within 16-dim vector
    bool fwd  = (og < 2);
    #pragma unroll
    for (int ei=0; ei<2; ei++){
        int e = Eb + 64*ei + eg;
        if (e >= E) continue;
        int idx = r*E + e;
        int src = __ldg(edge_src + idx);
        int dst = __ldg(edge_dst + idx);
        float b = g_blend[idx];
        float w = b * rsqrtf(g_norm_u[src]*g_norm_i[dst]);
        if (og == 0) out[NUU*DOUT + NII*DOUT + idx] = w;   // int_dist once

        const unsigned long long* cc = ei ? c1 : c0;
        float o8[8];
        #pragma unroll
        for (int q=0;q<4;q++) unpk2(cc[q], o8[2*q], o8[2*q+1]);

        if (fwd){
            const float4* hu = (const float4*)((const float*)g_hu
                               + ((size_t)r*NUU + src)*DN + oBase);
            float4 h0 = __ldg(hu), h1 = __ldg(hu+1);
            float4* t = (float4*)((float*)g_imsg + (size_t)dst*DN + oBase);
            red_add_v4(t,   make_float4((h0.x+o8[0])*w,(h0.y+o8[1])*w,
                                        (h0.z+o8[2])*w,(h0.w+o8[3])*w));
            red_add_v4(t+1, make_float4((h1.x+o8[4])*w,(h1.y+o8[5])*w,
                                        (h1.z+o8[6])*w,(h1.w+o8[7])*w));
        } else {
            const float4* hi = (const float4*)((const float*)g_hi
                               + ((size_t)r*NII + dst)*DN + oBase);
            float4 h0 = __ldg(hi), h1 = __ldg(hi+1);
            float4* t = (float4*)((float*)g_umsg + (size_t)src*DN + oBase);
            red_add_v4(t,   make_float4((h0.x+o8[0])*w,(h0.y+o8[1])*w,
                                        (h0.z+o8[2])*w,(h0.w+o8[3])*w));
            red_add_v4(t+1, make_float4((h1.x+o8[4])*w,(h1.y+o8[5])*w,
                                        (h1.z+o8[6])*w,(h1.w+o8[7])*w));
        }
    }
}

// ---------------- K4: leaky_relu + FC epilogue (4 outputs/thread, v4 store) ----
__global__ void __launch_bounds__(256) k_fc(
    const float* __restrict__ ufc_w, const float* __restrict__ ufc_b,
    const float* __restrict__ ifc_w, const float* __restrict__ ifc_b,
    float* __restrict__ out)
{
    __shared__ float Ws[DN*DOUT];   // transposed: Ws[j*64+o] = W[o*16+j]
    __shared__ float Bs[DOUT];
    int side = blockIdx.y;
    const float* W = side ? ifc_w : ufc_w;
    const float* B = side ? ifc_b : ufc_b;
    for (int i = threadIdx.x; i < DN*DOUT; i += 256){
        int o = i >> 4, j = i & 15;         // coalesced gmem read of W
        Ws[j*DOUT + o] = W[i];
    }
    if (threadIdx.x < DOUT) Bs[threadIdx.x] = B[threadIdx.x];
    __syncthreads();

    int idx = blockIdx.x*256 + threadIdx.x;   // < NUU*DOUT/4
    int n  = idx >> 4;
    int o4 = (idx & 15)*4;
    const float4* msg4 = (const float4*)((const float*)(side ? g_imsg : g_umsg) + (size_t)n*DN);
    float4 acc = *(const float4*)(Bs + o4);
    #pragma unroll
    for (int q=0;q<4;q++){
        float4 m = msg4[q];                  // warp-broadcast
        float xs[4] = {(m.x>0.f)?m.x:0.1f*m.x, (m.y>0.f)?m.y:0.1f*m.y,
                       (m.z>0.f)?m.z:0.1f*m.z, (m.w>0.f)?m.w:0.1f*m.w};
        #pragma unroll
        for (int t=0;t<4;t++){
            const float4 wv = *(const float4*)(Ws + (4*q+t)*DOUT + o4);
            acc.x += xs[t]*wv.x;  acc.y += xs[t]*wv.y;
            acc.z += xs[t]*wv.z;  acc.w += xs[t]*wv.w;
        }
    }
    *(float4*)(out + (size_t)side*NUU*DOUT + (size_t)n*DOUT + o4) = acc;
}

// ---------------- launch ----------------
extern "C" void kernel_launch(void* const* d_in, const int* in_sizes, int n_in,
                              void* d_out, int out_size)
{
    const float* user_h      = (const float*)d_in[0];
    const float* item_h      = (const float*)d_in[1];
    const float* user_hsum   = (const float*)d_in[2];
    const float* item_hsum   = (const float*)d_in[3];
    const float* review_feat = (const float*)d_in[4];
    const float* prototypes  = (const float*)d_in[5];
    const float* eta         = (const float*)d_in[6];
    const float* node_w_fwd  = (const float*)d_in[7];
    const float* review_w_fwd= (const float*)d_in[8];
    const float* node_w_rev  = (const float*)d_in[9];
    const float* review_w_rev= (const float*)d_in[10];
    const float* ufc_w       = (const float*)d_in[11];
    const float* ufc_b       = (const float*)d_in[12];
    const float* ifc_w       = (const float*)d_in[13];
    const float* ifc_b       = (const float*)d_in[14];
    const int*   edge_src    = (const int*)d_in[15];
    const int*   edge_dst    = (const int*)d_in[16];
    const int*   kp          = (const int*)d_in[17];
    float* out = (float*)d_out;

    k_nodes<<<dim3((NUU+255)/256, R, 2), 256>>>(user_h, item_h, node_w_fwd, node_w_rev, kp);
    k_blend<<<dim3((E+31)/32, R), 256>>>(user_h, item_h, user_hsum, item_hsum,
                                         review_feat, prototypes, eta,
                                         edge_src, edge_dst, kp);
    k_msg  <<<dim3((E+TILE_E-1)/TILE_E, R), 256>>>(review_feat, review_w_fwd, review_w_rev,
                                                   edge_src, edge_dst, kp, out);
    k_fc   <<<dim3((NUU*DOUT/4)/256, 2), 256>>>(ufc_w, ufc_b, ifc_w, ifc_b, out);
}

// round 15
// speedup vs baseline: 1.1352x; 1.0309x over previous
#include <cuda_runtime.h>

#define R    5
#define E    50000
#define NUU  20000
#define NII  20000
#define NF   4
#define DN   16
#define DR   64
#define DOUT 64
#define TILE_E 128

// ---------------- scratch (allocation-free: __device__ globals) ----------------
__device__ float4 g_hu[R*NUU*4];     // hu[r,n,0:16]
__device__ float4 g_hi[R*NII*4];
__device__ float  g_blend[R*E];
__device__ float  g_norm_u[NUU];
__device__ float  g_norm_i[NII];
__device__ float4 g_umsg[NUU*4];
__device__ float4 g_imsg[NII*4];

__device__ __forceinline__ float dot4(float4 a, float4 b){
    return a.x*b.x + a.y*b.y + a.z*b.z + a.w*b.w;
}

__device__ __forceinline__ void red_add_v4(float4* addr, float4 v){
    asm volatile("red.global.add.v4.f32 [%0], {%1,%2,%3,%4};"
                 :: "l"(addr), "f"(v.x), "f"(v.y), "f"(v.z), "f"(v.w)
                 : "memory");
}

// packed fp32x2 helpers (sm_103a; ptxas never auto-emits FFMA2)
__device__ __forceinline__ unsigned long long pk2(float x){
    unsigned long long r;
    asm("mov.b64 %0, {%1, %1};" : "=l"(r) : "f"(x));
    return r;
}
__device__ __forceinline__ void ffma2(unsigned long long &d,
                                      unsigned long long a, unsigned long long b){
    asm("fma.rn.f32x2 %0, %1, %2, %0;" : "+l"(d) : "l"(a), "l"(b));
}
__device__ __forceinline__ void unpk2(unsigned long long v, float &lo, float &hi){
    asm("mov.b64 {%0, %1}, %2;" : "=f"(lo), "=f"(hi) : "l"(v));
}

// ---------------- K1: hu/hi = node_h[k] @ node_w^T  (+ folded zeroing) ---------
__global__ void __launch_bounds__(256) k_nodes(
    const float* __restrict__ user_h, const float* __restrict__ item_h,
    const float* __restrict__ w_fwd,  const float* __restrict__ w_rev,
    const int*   __restrict__ kp)
{
    // folded k_zero: flat id over the whole (x,y,z) grid covers all accumulators
    {
        int gid = ((blockIdx.z*R + blockIdx.y)*gridDim.x + blockIdx.x)*256 + threadIdx.x;
        float4 z = make_float4(0.f,0.f,0.f,0.f);
        if (gid < NUU*4) g_umsg[gid] = z;
        if (gid < NII*4) g_imsg[gid] = z;
        if (gid < NUU)   g_norm_u[gid] = 0.f;
        if (gid < NII)   g_norm_i[gid] = 0.f;
    }

    __shared__ float Ws[DN*DN];
    int r = blockIdx.y, side = blockIdx.z;
    const float* W = side ? w_rev : w_fwd;
    Ws[threadIdx.x] = W[r*DN*DN + threadIdx.x];
    __syncthreads();
    int n = blockIdx.x*256 + threadIdx.x;
    if (n >= NUU) return;
    int kv = __ldg(kp);
    const float* hp = (side ? item_h : user_h) + ((size_t)(kv*R + r)*NUU + n)*DN;
    const float4* h4 = (const float4*)hp;
    float h[16];
    #pragma unroll
    for (int j=0;j<4;j++){
        float4 v = h4[j];
        h[4*j]=v.x; h[4*j+1]=v.y; h[4*j+2]=v.z; h[4*j+3]=v.w;
    }
    float4* out = (side ? g_hi : g_hu) + ((size_t)r*NUU + n)*4;
    #pragma unroll
    for (int q=0;q<4;q++){
        float acc[4];
        #pragma unroll
        for (int t=0;t<4;t++){
            int o = q*4+t;
            float a = 0.f;
            #pragma unroll
            for (int d=0; d<16; d++) a += h[d]*Ws[o*16+d];
            acc[t] = a;
        }
        out[q] = make_float4(acc[0],acc[1],acc[2],acc[3]);
    }
}

// ---------------- K2: blended weights, warp-cooperative (8 lanes / edge) ----------
__global__ void __launch_bounds__(256) k_blend(
    const float* __restrict__ user_h,    const float* __restrict__ item_h,
    const float* __restrict__ user_hsum, const float* __restrict__ item_hsum,
    const float* __restrict__ review_feat, const float* __restrict__ prototypes,
    const float* __restrict__ eta,
    const int*   __restrict__ edge_src,  const int* __restrict__ edge_dst,
    const int*   __restrict__ kp)
{
    __shared__ float4 Pr[NF*DR/4];   // 64 float4
    int r   = blockIdx.y;
    int tid = threadIdx.x;
    if (tid < NF*DR/4) Pr[tid] = ((const float4*)prototypes)[tid];
    __syncthreads();

    int g = tid >> 3;        // group (edge) within block: 0..31
    int l = tid & 7;         // lane within group
    int e = blockIdx.x*32 + g;
    bool valid = (e < E);
    int ec  = valid ? e : (E-1);      // clamp so shfl groups stay converged
    int idx = r*E + ec;
    int kv  = __ldg(kp);
    int src = __ldg(edge_src + idx);
    int dst = __ldg(edge_dst + idx);

    // ---- sim_k: cosine of user_h[k][r][src] vs item_h[k][r][dst] ----
    float uu=0.f, ii=0.f, ui=0.f;
    if (l < 4){
        float4 a = __ldg((const float4*)(user_h + ((size_t)(kv*R + r)*NUU + src)*DN) + l);
        float4 b = __ldg((const float4*)(item_h + ((size_t)(kv*R + r)*NII + dst)*DN) + l);
        uu = dot4(a,a); ii = dot4(b,b); ui = dot4(a,b);
    }
    #pragma unroll
    for (int s=1; s<8; s<<=1){
        uu += __shfl_xor_sync(0xffffffffu, uu, s, 8);
        ii += __shfl_xor_sync(0xffffffffu, ii, s, 8);
        ui += __shfl_xor_sync(0xffffffffu, ui, s, 8);
    }

    // ---- sim_all denominator: lane pair (2f,2f+1) handles factor f ----
    const float4* ru = (const float4*)(user_hsum + ((size_t)(r*NUU+src))*NF*DN);
    const float4* ci = (const float4*)(item_hsum + ((size_t)(r*NII+dst))*NF*DN);
    int off = (l>>1)*4 + (l&1)*2;
    float p = dot4(__ldg(ru+off),   __ldg(ci+off))
            + dot4(__ldg(ru+off+1), __ldg(ci+off+1));
    p += __shfl_xor_sync(0xffffffffu, p, 1, 8);     // full dot_f on both pair lanes
    float es = __expf(2.0f*p) * 0.5f;               // halve: each f counted twice
    es += __shfl_xor_sync(0xffffffffu, es, 1, 8);
    es += __shfl_xor_sync(0xffffffffu, es, 2, 8);
    es += __shfl_xor_sync(0xffffffffu, es, 4, 8);   // es = sum_f exp(sim_all_f)

    // ---- anchors: lane l covers float4s {2l, 2l+1} of each factor ----
    const float4* rf = (const float4*)(review_feat + (size_t)idx*NF*DR);
    float pa[NF];
    #pragma unroll
    for (int f=0; f<NF; f++){
        int o = f*16 + l*2;
        pa[f] = dot4(__ldg(rf+o),   Pr[o])
              + dot4(__ldg(rf+o+1), Pr[o+1]);
    }
    #pragma unroll
    for (int f=0; f<NF; f++){
        #pragma unroll
        for (int s=1; s<8; s<<=1)
            pa[f] += __shfl_xor_sync(0xffffffffu, pa[f], s, 8);
    }
    float dA = 0.f, aK = 0.f;
    #pragma unroll
    for (int f=0; f<NF; f++){
        float af = 2.0f*pa[f];
        dA += __expf(af);
        if (f == kv) aK = af;
    }

    if (l == 0 && valid){
        float den = fmaxf(sqrtf(uu),1e-12f) * fmaxf(sqrtf(ii),1e-12f);
        float sim_k = (ui/den) * 2.0f;
        float exp_sim    = __expf(sim_k)/es;
        float exp_anchor = __expf(aK)/dA;
        float et = __ldg(eta + idx);
        float gg = 1.0f/(1.0f + __expf(-et));
        float blended = gg*exp_anchor + (1.0f-gg)*exp_sim;
        g_blend[idx] = blended;
        atomicAdd(&g_norm_u[src], blended);
        atomicAdd(&g_norm_i[dst], blended);
    }
}

// ---------------- K3: register-blocked GEMM tile + scatter (R12/R10 shape) -----
// 256 threads = 64 edge-cols x 4 output-groups; thread C-tile = 2 edges x 8 outs.
__global__ void __launch_bounds__(256) k_msg(
    const float* __restrict__ review_feat,
    const float* __restrict__ rw_fwd, const float* __restrict__ rw_rev,
    const int*   __restrict__ edge_src, const int* __restrict__ edge_dst,
    const int*   __restrict__ kp, float* __restrict__ out)
{
    __shared__ float4 A4[TILE_E*17];      // 34816 B
    __shared__ float  Wc[DR*36];          //  9216 B
    int r   = blockIdx.y;
    int tid = threadIdx.x;
    int kv  = __ldg(kp);
    int Eb  = blockIdx.x*TILE_E;

    // stage weights: Wc[d][o] fwd at o, rev at 16+o  (coalesced gmem reads)
    for (int i = tid; i < DN*DR; i += 256){
        int o = i >> 6, d = i & 63;
        Wc[d*36 + o]      = rw_fwd[(size_t)r*DN*DR + i];
        Wc[d*36 + 16 + o] = rw_rev[(size_t)r*DN*DR + i];
    }
    // stage A tile (rf_k rows), coalesced 64B+ chunks
    for (int i = tid; i < TILE_E*16; i += 256){
        int row = i >> 4, col = i & 15;
        int er = Eb + row; if (er >= E) er = E-1;
        A4[row*17 + col] =
            __ldg((const float4*)(review_feat + ((size_t)(r*E+er)*NF + kv)*DR) + col);
    }
    __syncthreads();

    int og = tid >> 6;          // 0..3 : output group (8 outputs)
    int eg = tid & 63;          // 0..63: edge column
    const float4* a0 = &A4[eg*17];
    const float4* a1 = &A4[(64+eg)*17];
    const float*  Wb = Wc + og*8;

    unsigned long long c0[4], c1[4];
    #pragma unroll
    for (int q=0;q<4;q++){ c0[q]=0ull; c1[q]=0ull; }

    #pragma unroll 4
    for (int kq=0; kq<16; kq++){
        float4 x0 = a0[kq];
        float4 x1 = a1[kq];
        float s0[4] = {x0.x,x0.y,x0.z,x0.w};
        float s1[4] = {x1.x,x1.y,x1.z,x1.w};
        #pragma unroll
        for (int c=0;c<4;c++){
            const ulonglong2* b2 = (const ulonglong2*)(Wb + (4*kq+c)*36);
            ulonglong2 bA = b2[0];              // outputs og*8+0..3 (broadcast)
            ulonglong2 bB = b2[1];              // outputs og*8+4..7
            unsigned long long p0 = pk2(s0[c]);
            unsigned long long p1 = pk2(s1[c]);
            ffma2(c0[0], p0, bA.x); ffma2(c0[1], p0, bA.y);
            ffma2(c0[2], p0, bB.x); ffma2(c0[3], p0, bB.y);
            ffma2(c1[0], p1, bA.x); ffma2(c1[1], p1, bA.y);
            ffma2(c1[2], p1, bB.x); ffma2(c1[3], p1, bB.y);
        }
    }

    // ---- epilogue: each thread scatters its 8-float slice for its 2 edges ----
    int oBase = (og & 1)*8;                 // float offset within 16-dim vector
    bool fwd  = (og < 2);
    #pragma unroll
    for (int ei=0; ei<2; ei++){
        int e = Eb + 64*ei + eg;
        if (e >= E) continue;
        int idx = r*E + e;
        int src = __ldg(edge_src + idx);
        int dst = __ldg(edge_dst + idx);
        float b = g_blend[idx];
        float w = b * rsqrtf(g_norm_u[src]*g_norm_i[dst]);
        if (og == 0) out[NUU*DOUT + NII*DOUT + idx] = w;   // int_dist once

        const unsigned long long* cc = ei ? c1 : c0;
        float o8[8];
        #pragma unroll
        for (int q=0;q<4;q++) unpk2(cc[q], o8[2*q], o8[2*q+1]);

        if (fwd){
            const float4* hu = (const float4*)((const float*)g_hu
                               + ((size_t)r*NUU + src)*DN + oBase);
            float4 h0 = __ldg(hu), h1 = __ldg(hu+1);
            float4* t = (float4*)((float*)g_imsg + (size_t)dst*DN + oBase);
            red_add_v4(t,   make_float4((h0.x+o8[0])*w,(h0.y+o8[1])*w,
                                        (h0.z+o8[2])*w,(h0.w+o8[3])*w));
            red_add_v4(t+1, make_float4((h1.x+o8[4])*w,(h1.y+o8[5])*w,
                                        (h1.z+o8[6])*w,(h1.w+o8[7])*w));
        } else {
            const float4* hi = (const float4*)((const float*)g_hi
                               + ((size_t)r*NII + dst)*DN + oBase);
            float4 h0 = __ldg(hi), h1 = __ldg(hi+1);
            float4* t = (float4*)((float*)g_umsg + (size_t)src*DN + oBase);
            red_add_v4(t,   make_float4((h0.x+o8[0])*w,(h0.y+o8[1])*w,
                                        (h0.z+o8[2])*w,(h0.w+o8[3])*w));
            red_add_v4(t+1, make_float4((h1.x+o8[4])*w,(h1.y+o8[5])*w,
                                        (h1.z+o8[6])*w,(h1.w+o8[7])*w));
        }
    }
}

// ---------------- K4: leaky_relu + FC epilogue (2 nodes x 4 outputs/thread) ----
__global__ void __launch_bounds__(256) k_fc(
    const float* __restrict__ ufc_w, const float* __restrict__ ufc_b,
    const float* __restrict__ ifc_w, const float* __restrict__ ifc_b,
    float* __restrict__ out)
{
    __shared__ float Ws[DN*DOUT];   // transposed: Ws[j*64+o] = W[o*16+j]
    __shared__ float Bs[DOUT];
    int side = blockIdx.y;
    const float* W = side ? ifc_w : ufc_w;
    const float* B = side ? ifc_b : ufc_b;
    for (int i = threadIdx.x; i < DN*DOUT; i += 256){
        int o = i >> 4, j = i & 15;         // coalesced gmem read of W
        Ws[j*DOUT + o] = W[i];
    }
    if (threadIdx.x < DOUT) Bs[threadIdx.x] = B[threadIdx.x];
    __syncthreads();

    int idx = blockIdx.x*256 + threadIdx.x;   // < (NUU/2)*16
    int n0 = idx >> 4;                        // node pair: n0, n0+NUU/2
    int o4 = (idx & 15)*4;
    const float* base = (const float*)(side ? g_imsg : g_umsg);
    const float4* m0 = (const float4*)(base + (size_t)n0*DN);
    const float4* m1 = (const float4*)(base + (size_t)(n0 + NUU/2)*DN);
    float4 bias = *(const float4*)(Bs + o4);
    float4 acc0 = bias, acc1 = bias;
    #pragma unroll
    for (int q=0;q<4;q++){
        float4 ma = m0[q];                   // warp-broadcast
        float4 mb = m1[q];
        float xa[4] = {(ma.x>0.f)?ma.x:0.1f*ma.x, (ma.y>0.f)?ma.y:0.1f*ma.y,
                       (ma.z>0.f)?ma.z:0.1f*ma.z, (ma.w>0.f)?ma.w:0.1f*ma.w};
        float xb[4] = {(mb.x>0.f)?mb.x:0.1f*mb.x, (mb.y>0.f)?mb.y:0.1f*mb.y,
                       (mb.z>0.f)?mb.z:0.1f*mb.z, (mb.w>0.f)?mb.w:0.1f*mb.w};
        #pragma unroll
        for (int t=0;t<4;t++){
            const float4 wv = *(const float4*)(Ws + (4*q+t)*DOUT + o4);  // reused
            acc0.x += xa[t]*wv.x;  acc0.y += xa[t]*wv.y;
            acc0.z += xa[t]*wv.z;  acc0.w += xa[t]*wv.w;
            acc1.x += xb[t]*wv.x;  acc1.y += xb[t]*wv.y;
            acc1.z += xb[t]*wv.z;  acc1.w += xb[t]*wv.w;
        }
    }
    float* ob = out + (size_t)side*NUU*DOUT;
    *(float4*)(ob + (size_t)n0*DOUT + o4)             = acc0;
    *(float4*)(ob + (size_t)(n0+NUU/2)*DOUT + o4)     = acc1;
}

// ---------------- launch ----------------
extern "C" void kernel_launch(void* const* d_in, const int* in_sizes, int n_in,
                              void* d_out, int out_size)
{
    const float* user_h      = (const float*)d_in[0];
    const float* item_h      = (const float*)d_in[1];
    const float* user_hsum   = (const float*)d_in[2];
    const float* item_hsum   = (const float*)d_in[3];
    const float* review_feat = (const float*)d_in[4];
    const float* prototypes  = (const float*)d_in[5];
    const float* eta         = (const float*)d_in[6];
    const float* node_w_fwd  = (const float*)d_in[7];
    const float* review_w_fwd= (const float*)d_in[8];
    const float* node_w_rev  = (const float*)d_in[9];
    const float* review_w_rev= (const float*)d_in[10];
    const float* ufc_w       = (const float*)d_in[11];
    const float* ufc_b       = (const float*)d_in[12];
    const float* ifc_w       = (const float*)d_in[13];
    const float* ifc_b       = (const float*)d_in[14];
    const int*   edge_src    = (const int*)d_in[15];
    const int*   edge_dst    = (const int*)d_in[16];
    const int*   kp          = (const int*)d_in[17];
    float* out = (float*)d_out;

    k_nodes<<<dim3((NUU+255)/256, R, 2), 256>>>(user_h, item_h, node_w_fwd, node_w_rev, kp);
    k_blend<<<dim3((E+31)/32, R), 256>>>(user_h, item_h, user_hsum, item_hsum,
                                         review_feat, prototypes, eta,
                                         edge_src, edge_dst, kp);
    k_msg  <<<dim3((E+TILE_E-1)/TILE_E, R), 256>>>(review_feat, review_w_fwd, review_w_rev,
                                                   edge_src, edge_dst, kp, out);
    k_fc   <<<dim3(((NUU/2)*16)/256, 2), 256>>>(ufc_w, ufc_b, ifc_w, ifc_b, out);
}

// round 16
// speedup vs baseline: 1.1488x; 1.0120x over previous
#include <cuda_runtime.h>

#define R    5
#define E    50000
#define NUU  20000
#define NII  20000
#define NF   4
#define DN   16
#define DR   64
#define DOUT 64
#define TILE_E 128

// ---------------- scratch (allocation-free: __device__ globals) ----------------
__device__ float4 g_hu[R*NUU*4];     // hu[r,n,0:16]
__device__ float4 g_hi[R*NII*4];
__device__ float  g_blend[R*E];
__device__ float  g_norm_u[NUU];
__device__ float  g_norm_i[NII];
__device__ float4 g_umsg[NUU*4];
__device__ float4 g_imsg[NII*4];

__device__ __forceinline__ float dot4(float4 a, float4 b){
    return a.x*b.x + a.y*b.y + a.z*b.z + a.w*b.w;
}

__device__ __forceinline__ void red_add_v4(float4* addr, float4 v){
    asm volatile("red.global.add.v4.f32 [%0], {%1,%2,%3,%4};"
                 :: "l"(addr), "f"(v.x), "f"(v.y), "f"(v.z), "f"(v.w)
                 : "memory");
}

// packed fp32x2 helpers (sm_103a; ptxas never auto-emits FFMA2)
__device__ __forceinline__ unsigned long long pk2(float x){
    unsigned long long r;
    asm("mov.b64 %0, {%1, %1};" : "=l"(r) : "f"(x));
    return r;
}
__device__ __forceinline__ void ffma2(unsigned long long &d,
                                      unsigned long long a, unsigned long long b){
    asm("fma.rn.f32x2 %0, %1, %2, %0;" : "+l"(d) : "l"(a), "l"(b));
}
__device__ __forceinline__ void unpk2(unsigned long long v, float &lo, float &hi){
    asm("mov.b64 {%0, %1}, %2;" : "=f"(lo), "=f"(hi) : "l"(v));
}

// ---------------- K1: hu/hi = node_h[k] @ node_w^T  (+ folded zeroing) ---------
__global__ void __launch_bounds__(256) k_nodes(
    const float* __restrict__ user_h, const float* __restrict__ item_h,
    const float* __restrict__ w_fwd,  const float* __restrict__ w_rev,
    const int*   __restrict__ kp)
{
    // folded k_zero: flat id over the whole (x,y,z) grid covers all accumulators
    {
        int gid = ((blockIdx.z*R + blockIdx.y)*gridDim.x + blockIdx.x)*256 + threadIdx.x;
        float4 z = make_float4(0.f,0.f,0.f,0.f);
        if (gid < NUU*4) g_umsg[gid] = z;
        if (gid < NII*4) g_imsg[gid] = z;
        if (gid < NUU)   g_norm_u[gid] = 0.f;
        if (gid < NII)   g_norm_i[gid] = 0.f;
    }

    __shared__ float Ws[DN*DN];
    int r = blockIdx.y, side = blockIdx.z;
    const float* W = side ? w_rev : w_fwd;
    Ws[threadIdx.x] = W[r*DN*DN + threadIdx.x];
    __syncthreads();
    int n = blockIdx.x*256 + threadIdx.x;
    if (n >= NUU) return;
    int kv = __ldg(kp);
    const float* hp = (side ? item_h : user_h) + ((size_t)(kv*R + r)*NUU + n)*DN;
    const float4* h4 = (const float4*)hp;
    float h[16];
    #pragma unroll
    for (int j=0;j<4;j++){
        float4 v = h4[j];
        h[4*j]=v.x; h[4*j+1]=v.y; h[4*j+2]=v.z; h[4*j+3]=v.w;
    }
    float4* out = (side ? g_hi : g_hu) + ((size_t)r*NUU + n)*4;
    #pragma unroll
    for (int q=0;q<4;q++){
        float acc[4];
        #pragma unroll
        for (int t=0;t<4;t++){
            int o = q*4+t;
            float a = 0.f;
            #pragma unroll
            for (int d=0; d<16; d++) a += h[d]*Ws[o*16+d];
            acc[t] = a;
        }
        out[q] = make_float4(acc[0],acc[1],acc[2],acc[3]);
    }
}

// ---------------- K2: blended weights, warp-cooperative (8 lanes / edge) --------
// Gathers restructured for contiguity: within each 8-lane group, every LDG.128
// covers a 128B-contiguous span (lane l -> float4 l and l+8).
__global__ void __launch_bounds__(256) k_blend(
    const float* __restrict__ user_h,    const float* __restrict__ item_h,
    const float* __restrict__ user_hsum, const float* __restrict__ item_hsum,
    const float* __restrict__ review_feat, const float* __restrict__ prototypes,
    const float* __restrict__ eta,
    const int*   __restrict__ edge_src,  const int* __restrict__ edge_dst,
    const int*   __restrict__ kp)
{
    __shared__ float4 Pr[NF*DR/4];   // 64 float4
    int r   = blockIdx.y;
    int tid = threadIdx.x;
    if (tid < NF*DR/4) Pr[tid] = ((const float4*)prototypes)[tid];
    __syncthreads();

    int g = tid >> 3;        // group (edge) within block: 0..31
    int l = tid & 7;         // lane within group
    int e = blockIdx.x*32 + g;
    bool valid = (e < E);
    int ec  = valid ? e : (E-1);      // clamp so shfl groups stay converged
    int idx = r*E + ec;
    int kv  = __ldg(kp);
    int src = __ldg(edge_src + idx);
    int dst = __ldg(edge_dst + idx);

    // ---- sim_k: cosine of user_h[k][r][src] vs item_h[k][r][dst] ----
    float uu=0.f, ii=0.f, ui=0.f;
    if (l < 4){
        float4 a = __ldg((const float4*)(user_h + ((size_t)(kv*R + r)*NUU + src)*DN) + l);
        float4 b = __ldg((const float4*)(item_h + ((size_t)(kv*R + r)*NII + dst)*DN) + l);
        uu = dot4(a,a); ii = dot4(b,b); ui = dot4(a,b);
    }
    #pragma unroll
    for (int s=1; s<8; s<<=1){
        uu += __shfl_xor_sync(0xffffffffu, uu, s, 8);
        ii += __shfl_xor_sync(0xffffffffu, ii, s, 8);
        ui += __shfl_xor_sync(0xffffffffu, ui, s, 8);
    }

    // ---- sim_all denominator: lane l handles flat float4s l and l+8 ----
    // float4 l belongs to factor l>>2; float4 l+8 to factor 2+(l>>2).
    const float4* ru = (const float4*)(user_hsum + ((size_t)(r*NUU+src))*NF*DN);
    const float4* ci = (const float4*)(item_hsum + ((size_t)(r*NII+dst))*NF*DN);
    float p = dot4(__ldg(ru+l),   __ldg(ci+l));     // factor l>>2      (0 or 1)
    float q = dot4(__ldg(ru+l+8), __ldg(ci+l+8));   // factor 2+(l>>2)  (2 or 3)
    // reduce within 4-lane subgroups (xor 1,2 preserve l>>2)
    p += __shfl_xor_sync(0xffffffffu, p, 1, 8);
    q += __shfl_xor_sync(0xffffffffu, q, 1, 8);
    p += __shfl_xor_sync(0xffffffffu, p, 2, 8);
    q += __shfl_xor_sync(0xffffffffu, q, 2, 8);
    float es = __expf(2.0f*p) + __expf(2.0f*q);     // two factors per half
    es += __shfl_xor_sync(0xffffffffu, es, 4, 8);   // es = sum_f exp(sim_all_f)

    // ---- anchors: lane l covers float4s {l, l+8} of each factor (contiguous) ----
    const float4* rf = (const float4*)(review_feat + (size_t)idx*NF*DR);
    float pa[NF];
    #pragma unroll
    for (int f=0; f<NF; f++){
        int o = f*16 + l;
        pa[f] = dot4(__ldg(rf+o),   Pr[o])
              + dot4(__ldg(rf+o+8), Pr[o+8]);
    }
    #pragma unroll
    for (int f=0; f<NF; f++){
        #pragma unroll
        for (int s=1; s<8; s<<=1)
            pa[f] += __shfl_xor_sync(0xffffffffu, pa[f], s, 8);
    }
    float dA = 0.f, aK = 0.f;
    #pragma unroll
    for (int f=0; f<NF; f++){
        float af = 2.0f*pa[f];
        dA += __expf(af);
        if (f == kv) aK = af;
    }

    if (l == 0 && valid){
        float den = fmaxf(sqrtf(uu),1e-12f) * fmaxf(sqrtf(ii),1e-12f);
        float sim_k = (ui/den) * 2.0f;
        float exp_sim    = __expf(sim_k)/es;
        float exp_anchor = __expf(aK)/dA;
        float et = __ldg(eta + idx);
        float gg = 1.0f/(1.0f + __expf(-et));
        float blended = gg*exp_anchor + (1.0f-gg)*exp_sim;
        g_blend[idx] = blended;
        atomicAdd(&g_norm_u[src], blended);
        atomicAdd(&g_norm_i[dst], blended);
    }
}

// ---------------- K3: register-blocked GEMM tile + scatter (R12/R10 shape) -----
// 256 threads = 64 edge-cols x 4 output-groups; thread C-tile = 2 edges x 8 outs.
__global__ void __launch_bounds__(256) k_msg(
    const float* __restrict__ review_feat,
    const float* __restrict__ rw_fwd, const float* __restrict__ rw_rev,
    const int*   __restrict__ edge_src, const int* __restrict__ edge_dst,
    const int*   __restrict__ kp, float* __restrict__ out)
{
    __shared__ float4 A4[TILE_E*17];      // 34816 B
    __shared__ float  Wc[DR*36];          //  9216 B
    int r   = blockIdx.y;
    int tid = threadIdx.x;
    int kv  = __ldg(kp);
    int Eb  = blockIdx.x*TILE_E;

    // stage weights: Wc[d][o] fwd at o, rev at 16+o  (coalesced gmem reads)
    for (int i = tid; i < DN*DR; i += 256){
        int o = i >> 6, d = i & 63;
        Wc[d*36 + o]      = rw_fwd[(size_t)r*DN*DR + i];
        Wc[d*36 + 16 + o] = rw_rev[(size_t)r*DN*DR + i];
    }
    // stage A tile (rf_k rows), coalesced 64B+ chunks
    for (int i = tid; i < TILE_E*16; i += 256){
        int row = i >> 4, col = i & 15;
        int er = Eb + row; if (er >= E) er = E-1;
        A4[row*17 + col] =
            __ldg((const float4*)(review_feat + ((size_t)(r*E+er)*NF + kv)*DR) + col);
    }
    __syncthreads();

    int og = tid >> 6;          // 0..3 : output group (8 outputs)
    int eg = tid & 63;          // 0..63: edge column
    const float4* a0 = &A4[eg*17];
    const float4* a1 = &A4[(64+eg)*17];
    const float*  Wb = Wc + og*8;

    unsigned long long c0[4], c1[4];
    #pragma unroll
    for (int q=0;q<4;q++){ c0[q]=0ull; c1[q]=0ull; }

    #pragma unroll 4
    for (int kq=0; kq<16; kq++){
        float4 x0 = a0[kq];
        float4 x1 = a1[kq];
        float s0[4] = {x0.x,x0.y,x0.z,x0.w};
        float s1[4] = {x1.x,x1.y,x1.z,x1.w};
        #pragma unroll
        for (int c=0;c<4;c++){
            const ulonglong2* b2 = (const ulonglong2*)(Wb + (4*kq+c)*36);
            ulonglong2 bA = b2[0];              // outputs og*8+0..3 (broadcast)
            ulonglong2 bB = b2[1];              // outputs og*8+4..7
            unsigned long long p0 = pk2(s0[c]);
            unsigned long long p1 = pk2(s1[c]);
            ffma2(c0[0], p0, bA.x); ffma2(c0[1], p0, bA.y);
            ffma2(c0[2], p0, bB.x); ffma2(c0[3], p0, bB.y);
            ffma2(c1[0], p1, bA.x); ffma2(c1[1], p1, bA.y);
            ffma2(c1[2], p1, bB.x); ffma2(c1[3], p1, bB.y);
        }
    }

    // ---- epilogue: each thread scatters its 8-float slice for its 2 edges ----
    int oBase = (og & 1)*8;                 // float offset within 16-dim vector
    bool fwd  = (og < 2);
    #pragma unroll
    for (int ei=0; ei<2; ei++){
        int e = Eb + 64*ei + eg;
        if (e >= E) continue;
        int idx = r*E + e;
        int src = __ldg(edge_src + idx);
        int dst = __ldg(edge_dst + idx);
        float b = g_blend[idx];
        float w = b * rsqrtf(g_norm_u[src]*g_norm_i[dst]);
        if (og == 0) out[NUU*DOUT + NII*DOUT + idx] = w;   // int_dist once

        const unsigned long long* cc = ei ? c1 : c0;
        float o8[8];
        #pragma unroll
        for (int q=0;q<4;q++) unpk2(cc[q], o8[2*q], o8[2*q+1]);

        if (fwd){
            const float4* hu = (const float4*)((const float*)g_hu
                               + ((size_t)r*NUU + src)*DN + oBase);
            float4 h0 = __ldg(hu), h1 = __ldg(hu+1);
            float4* t = (float4*)((float*)g_imsg + (size_t)dst*DN + oBase);
            red_add_v4(t,   make_float4((h0.x+o8[0])*w,(h0.y+o8[1])*w,
                                        (h0.z+o8[2])*w,(h0.w+o8[3])*w));
            red_add_v4(t+1, make_float4((h1.x+o8[4])*w,(h1.y+o8[5])*w,
                                        (h1.z+o8[6])*w,(h1.w+o8[7])*w));
        } else {
            const float4* hi = (const float4*)((const float*)g_hi
                               + ((size_t)r*NII + dst)*DN + oBase);
            float4 h0 = __ldg(hi), h1 = __ldg(hi+1);
            float4* t = (float4*)((float*)g_umsg + (size_t)src*DN + oBase);
            red_add_v4(t,   make_float4((h0.x+o8[0])*w,(h0.y+o8[1])*w,
                                        (h0.z+o8[2])*w,(h0.w+o8[3])*w));
            red_add_v4(t+1, make_float4((h1.x+o8[4])*w,(h1.y+o8[5])*w,
                                        (h1.z+o8[6])*w,(h1.w+o8[7])*w));
        }
    }
}

// ---------------- K4: leaky_relu + FC epilogue (2 nodes x 4 outputs/thread) ----
__global__ void __launch_bounds__(256) k_fc(
    const float* __restrict__ ufc_w, const float* __restrict__ ufc_b,
    const float* __restrict__ ifc_w, const float* __restrict__ ifc_b,
    float* __restrict__ out)
{
    __shared__ float Ws[DN*DOUT];   // transposed: Ws[j*64+o] = W[o*16+j]
    __shared__ float Bs[DOUT];
    int side = blockIdx.y;
    const float* W = side ? ifc_w : ufc_w;
    const float* B = side ? ifc_b : ufc_b;
    for (int i = threadIdx.x; i < DN*DOUT; i += 256){
        int o = i >> 4, j = i & 15;         // coalesced gmem read of W
        Ws[j*DOUT + o] = W[i];
    }
    if (threadIdx.x < DOUT) Bs[threadIdx.x] = B[threadIdx.x];
    __syncthreads();

    int idx = blockIdx.x*256 + threadIdx.x;   // < (NUU/2)*16
    int n0 = idx >> 4;                        // node pair: n0, n0+NUU/2
    int o4 = (idx & 15)*4;
    const float* base = (const float*)(side ? g_imsg : g_umsg);
    const float4* m0 = (const float4*)(base + (size_t)n0*DN);
    const float4* m1 = (const float4*)(base + (size_t)(n0 + NUU/2)*DN);
    float4 bias = *(const float4*)(Bs + o4);
    float4 acc0 = bias, acc1 = bias;
    #pragma unroll
    for (int q=0;q<4;q++){
        float4 ma = m0[q];                   // warp-broadcast
        float4 mb = m1[q];
        float xa[4] = {(ma.x>0.f)?ma.x:0.1f*ma.x, (ma.y>0.f)?ma.y:0.1f*ma.y,
                       (ma.z>0.f)?ma.z:0.1f*ma.z, (ma.w>0.f)?ma.w:0.1f*ma.w};
        float xb[4] = {(mb.x>0.f)?mb.x:0.1f*mb.x, (mb.y>0.f)?mb.y:0.1f*mb.y,
                       (mb.z>0.f)?mb.z:0.1f*mb.z, (mb.w>0.f)?mb.w:0.1f*mb.w};
        #pragma unroll
        for (int t=0;t<4;t++){
            const float4 wv = *(const float4*)(Ws + (4*q+t)*DOUT + o4);  // reused
            acc0.x += xa[t]*wv.x;  acc0.y += xa[t]*wv.y;
            acc0.z += xa[t]*wv.z;  acc0.w += xa[t]*wv.w;
            acc1.x += xb[t]*wv.x;  acc1.y += xb[t]*wv.y;
            acc1.z += xb[t]*wv.z;  acc1.w += xb[t]*wv.w;
        }
    }
    float* ob = out + (size_t)side*NUU*DOUT;
    *(float4*)(ob + (size_t)n0*DOUT + o4)             = acc0;
    *(float4*)(ob + (size_t)(n0+NUU/2)*DOUT + o4)     = acc1;
}

// ---------------- launch ----------------
extern "C" void kernel_launch(void* const* d_in, const int* in_sizes, int n_in,
                              void* d_out, int out_size)
{
    const float* user_h      = (const float*)d_in[0];
    const float* item_h      = (const float*)d_in[1];
    const float* user_hsum   = (const float*)d_in[2];
    const float* item_hsum   = (const float*)d_in[3];
    const float* review_feat = (const float*)d_in[4];
    const float* prototypes  = (const float*)d_in[5];
    const float* eta         = (const float*)d_in[6];
    const float* node_w_fwd  = (const float*)d_in[7];
    const float* review_w_fwd= (const float*)d_in[8];
    const float* node_w_rev  = (const float*)d_in[9];
    const float* review_w_rev= (const float*)d_in[10];
    const float* ufc_w       = (const float*)d_in[11];
    const float* ufc_b       = (const float*)d_in[12];
    const float* ifc_w       = (const float*)d_in[13];
    const float* ifc_b       = (const float*)d_in[14];
    const int*   edge_src    = (const int*)d_in[15];
    const int*   edge_dst    = (const int*)d_in[16];
    const int*   kp          = (const int*)d_in[17];
    float* out = (float*)d_out;

    k_nodes<<<dim3((NUU+255)/256, R, 2), 256>>>(user_h, item_h, node_w_fwd, node_w_rev, kp);
    k_blend<<<dim3((E+31)/32, R), 256>>>(user_h, item_h, user_hsum, item_hsum,
                                         review_feat, prototypes, eta,
                                         edge_src, edge_dst, kp);
    k_msg  <<<dim3((E+TILE_E-1)/TILE_E, R), 256>>>(review_feat, review_w_fwd, review_w_rev,
                                                   edge_src, edge_dst, kp, out);
    k_fc   <<<dim3(((NUU/2)*16)/256, 2), 256>>>(ufc_w, ufc_b, ifc_w, ifc_b, out);
}

// round 17
// speedup vs baseline: 1.1686x; 1.0172x over previous
#include <cuda_runtime.h>

#define R    5
#define E    50000
#define NUU  20000
#define NII  20000
#define NF   4
#define DN   16
#define DR   64
#define DOUT 64
#define TILE_E 128
#define BLEND_BX 1563          // (E+31)/32
#define NODE_BX  79            // (NUU+255)/256

// ---------------- scratch (allocation-free: __device__ globals) ----------------
// NOTE: zero-initialized at module load; k_fc restores zeros each run so every
// kernel_launch starts from the same state (self-restoring invariant).
__device__ float4 g_hu[R*NUU*4];     // hu[r,n,0:16]
__device__ float4 g_hi[R*NII*4];
__device__ float  g_blend[R*E];
__device__ __align__(16) float g_norm_u[NUU];
__device__ __align__(16) float g_norm_i[NII];
__device__ float4 g_umsg[NUU*4];
__device__ float4 g_imsg[NII*4];

__device__ __forceinline__ float dot4(float4 a, float4 b){
    return a.x*b.x + a.y*b.y + a.z*b.z + a.w*b.w;
}

__device__ __forceinline__ void red_add_v4(float4* addr, float4 v){
    asm volatile("red.global.add.v4.f32 [%0], {%1,%2,%3,%4};"
                 :: "l"(addr), "f"(v.x), "f"(v.y), "f"(v.z), "f"(v.w)
                 : "memory");
}

// packed fp32x2 helpers (sm_103a; ptxas never auto-emits FFMA2)
__device__ __forceinline__ unsigned long long pk2(float x){
    unsigned long long r;
    asm("mov.b64 %0, {%1, %1};" : "=l"(r) : "f"(x));
    return r;
}
__device__ __forceinline__ void ffma2(unsigned long long &d,
                                      unsigned long long a, unsigned long long b){
    asm("fma.rn.f32x2 %0, %1, %2, %0;" : "+l"(d) : "l"(a), "l"(b));
}
__device__ __forceinline__ void unpk2(unsigned long long v, float &lo, float &hi){
    asm("mov.b64 {%0, %1}, %2;" : "=f"(lo), "=f"(hi) : "l"(v));
}

// ---------------- K1: fused blend (x<BLEND_BX) + node transform (x>=BLEND_BX) ---
__global__ void __launch_bounds__(256) k_fuse(
    const float* __restrict__ user_h,    const float* __restrict__ item_h,
    const float* __restrict__ user_hsum, const float* __restrict__ item_hsum,
    const float* __restrict__ review_feat, const float* __restrict__ prototypes,
    const float* __restrict__ eta,
    const float* __restrict__ w_fwd,     const float* __restrict__ w_rev,
    const int*   __restrict__ edge_src,  const int* __restrict__ edge_dst,
    const int*   __restrict__ kp)
{
    __shared__ float4 Pr[NF*DR/4];   // blend path (1KB)
    __shared__ float  Ws[DN*DN];     // nodes path (1KB)
    int r   = blockIdx.y;
    int tid = threadIdx.x;
    int kv  = __ldg(kp);

    if (blockIdx.x >= BLEND_BX){
        // ---------------- nodes part: hu/hi = node_h[k] @ node_w^T ----------------
        int xb   = blockIdx.x - BLEND_BX;
        int side = xb / NODE_BX;
        int nb   = xb - side*NODE_BX;
        const float* W = side ? w_rev : w_fwd;
        Ws[tid] = W[r*DN*DN + tid];
        __syncthreads();
        int n = nb*256 + tid;
        if (n >= NUU) return;
        const float* hp = (side ? item_h : user_h) + ((size_t)(kv*R + r)*NUU + n)*DN;
        const float4* h4 = (const float4*)hp;
        float h[16];
        #pragma unroll
        for (int j=0;j<4;j++){
            float4 v = h4[j];
            h[4*j]=v.x; h[4*j+1]=v.y; h[4*j+2]=v.z; h[4*j+3]=v.w;
        }
        float4* outp = (side ? g_hi : g_hu) + ((size_t)r*NUU + n)*4;
        #pragma unroll
        for (int q=0;q<4;q++){
            float acc[4];
            #pragma unroll
            for (int t=0;t<4;t++){
                int o = q*4+t;
                float a = 0.f;
                #pragma unroll
                for (int d=0; d<16; d++) a += h[d]*Ws[o*16+d];
                acc[t] = a;
            }
            outp[q] = make_float4(acc[0],acc[1],acc[2],acc[3]);
        }
        return;
    }

    // ---------------- blend part: warp-cooperative (8 lanes / edge) -------------
    if (tid < NF*DR/4) Pr[tid] = ((const float4*)prototypes)[tid];
    __syncthreads();

    int g = tid >> 3;        // group (edge) within block: 0..31
    int l = tid & 7;         // lane within group
    int e = blockIdx.x*32 + g;
    bool valid = (e < E);
    int ec  = valid ? e : (E-1);      // clamp so shfl groups stay converged
    int idx = r*E + ec;
    int src = __ldg(edge_src + idx);
    int dst = __ldg(edge_dst + idx);

    // ---- sim_k: cosine of user_h[k][r][src] vs item_h[k][r][dst] ----
    float uu=0.f, ii=0.f, ui=0.f;
    if (l < 4){
        float4 a = __ldg((const float4*)(user_h + ((size_t)(kv*R + r)*NUU + src)*DN) + l);
        float4 b = __ldg((const float4*)(item_h + ((size_t)(kv*R + r)*NII + dst)*DN) + l);
        uu = dot4(a,a); ii = dot4(b,b); ui = dot4(a,b);
    }
    #pragma unroll
    for (int s=1; s<8; s<<=1){
        uu += __shfl_xor_sync(0xffffffffu, uu, s, 8);
        ii += __shfl_xor_sync(0xffffffffu, ii, s, 8);
        ui += __shfl_xor_sync(0xffffffffu, ui, s, 8);
    }

    // ---- sim_all denominator: lane l handles flat float4s l and l+8 ----
    const float4* ru = (const float4*)(user_hsum + ((size_t)(r*NUU+src))*NF*DN);
    const float4* ci = (const float4*)(item_hsum + ((size_t)(r*NII+dst))*NF*DN);
    float p = dot4(__ldg(ru+l),   __ldg(ci+l));     // factor l>>2      (0 or 1)
    float q = dot4(__ldg(ru+l+8), __ldg(ci+l+8));   // factor 2+(l>>2)  (2 or 3)
    p += __shfl_xor_sync(0xffffffffu, p, 1, 8);
    q += __shfl_xor_sync(0xffffffffu, q, 1, 8);
    p += __shfl_xor_sync(0xffffffffu, p, 2, 8);
    q += __shfl_xor_sync(0xffffffffu, q, 2, 8);
    float es = __expf(2.0f*p) + __expf(2.0f*q);     // two factors per half
    es += __shfl_xor_sync(0xffffffffu, es, 4, 8);   // es = sum_f exp(sim_all_f)

    // ---- anchors: lane l covers float4s {l, l+8} of each factor (contiguous) ----
    const float4* rf = (const float4*)(review_feat + (size_t)idx*NF*DR);
    float pa[NF];
    #pragma unroll
    for (int f=0; f<NF; f++){
        int o = f*16 + l;
        pa[f] = dot4(__ldg(rf+o),   Pr[o])
              + dot4(__ldg(rf+o+8), Pr[o+8]);
    }
    #pragma unroll
    for (int f=0; f<NF; f++){
        #pragma unroll
        for (int s=1; s<8; s<<=1)
            pa[f] += __shfl_xor_sync(0xffffffffu, pa[f], s, 8);
    }
    float dA = 0.f, aK = 0.f;
    #pragma unroll
    for (int f=0; f<NF; f++){
        float af = 2.0f*pa[f];
        dA += __expf(af);
        if (f == kv) aK = af;
    }

    if (l == 0 && valid){
        float den = fmaxf(sqrtf(uu),1e-12f) * fmaxf(sqrtf(ii),1e-12f);
        float sim_k = (ui/den) * 2.0f;
        float exp_sim    = __expf(sim_k)/es;
        float exp_anchor = __expf(aK)/dA;
        float et = __ldg(eta + idx);
        float gg = 1.0f/(1.0f + __expf(-et));
        float blended = gg*exp_anchor + (1.0f-gg)*exp_sim;
        g_blend[idx] = blended;
        atomicAdd(&g_norm_u[src], blended);
        atomicAdd(&g_norm_i[dst], blended);
    }
}

// ---------------- K2: register-blocked GEMM tile + scatter (frozen R12 shape) --
// 256 threads = 64 edge-cols x 4 output-groups; thread C-tile = 2 edges x 8 outs.
__global__ void __launch_bounds__(256) k_msg(
    const float* __restrict__ review_feat,
    const float* __restrict__ rw_fwd, const float* __restrict__ rw_rev,
    const int*   __restrict__ edge_src, const int* __restrict__ edge_dst,
    const int*   __restrict__ kp, float* __restrict__ out)
{
    __shared__ float4 A4[TILE_E*17];      // 34816 B
    __shared__ float  Wc[DR*36];          //  9216 B
    int r   = blockIdx.y;
    int tid = threadIdx.x;
    int kv  = __ldg(kp);
    int Eb  = blockIdx.x*TILE_E;

    for (int i = tid; i < DN*DR; i += 256){
        int o = i >> 6, d = i & 63;
        Wc[d*36 + o]      = rw_fwd[(size_t)r*DN*DR + i];
        Wc[d*36 + 16 + o] = rw_rev[(size_t)r*DN*DR + i];
    }
    for (int i = tid; i < TILE_E*16; i += 256){
        int row = i >> 4, col = i & 15;
        int er = Eb + row; if (er >= E) er = E-1;
        A4[row*17 + col] =
            __ldg((const float4*)(review_feat + ((size_t)(r*E+er)*NF + kv)*DR) + col);
    }
    __syncthreads();

    int og = tid >> 6;          // 0..3 : output group (8 outputs)
    int eg = tid & 63;          // 0..63: edge column
    const float4* a0 = &A4[eg*17];
    const float4* a1 = &A4[(64+eg)*17];
    const float*  Wb = Wc + og*8;

    unsigned long long c0[4], c1[4];
    #pragma unroll
    for (int q=0;q<4;q++){ c0[q]=0ull; c1[q]=0ull; }

    #pragma unroll 4
    for (int kq=0; kq<16; kq++){
        float4 x0 = a0[kq];
        float4 x1 = a1[kq];
        float s0[4] = {x0.x,x0.y,x0.z,x0.w};
        float s1[4] = {x1.x,x1.y,x1.z,x1.w};
        #pragma unroll
        for (int c=0;c<4;c++){
            const ulonglong2* b2 = (const ulonglong2*)(Wb + (4*kq+c)*36);
            ulonglong2 bA = b2[0];              // outputs og*8+0..3 (broadcast)
            ulonglong2 bB = b2[1];              // outputs og*8+4..7
            unsigned long long p0 = pk2(s0[c]);
            unsigned long long p1 = pk2(s1[c]);
            ffma2(c0[0], p0, bA.x); ffma2(c0[1], p0, bA.y);
            ffma2(c0[2], p0, bB.x); ffma2(c0[3], p0, bB.y);
            ffma2(c1[0], p1, bA.x); ffma2(c1[1], p1, bA.y);
            ffma2(c1[2], p1, bB.x); ffma2(c1[3], p1, bB.y);
        }
    }

    int oBase = (og & 1)*8;                 // float offset within 16-dim vector
    bool fwd  = (og < 2);
    #pragma unroll
    for (int ei=0; ei<2; ei++){
        int e = Eb + 64*ei + eg;
        if (e >= E) continue;
        int idx = r*E + e;
        int src = __ldg(edge_src + idx);
        int dst = __ldg(edge_dst + idx);
        float b = g_blend[idx];
        float w = b * rsqrtf(g_norm_u[src]*g_norm_i[dst]);
        if (og == 0) out[NUU*DOUT + NII*DOUT + idx] = w;   // int_dist once

        const unsigned long long* cc = ei ? c1 : c0;
        float o8[8];
        #pragma unroll
        for (int q=0;q<4;q++) unpk2(cc[q], o8[2*q], o8[2*q+1]);

        if (fwd){
            const float4* hu = (const float4*)((const float*)g_hu
                               + ((size_t)r*NUU + src)*DN + oBase);
            float4 h0 = __ldg(hu), h1 = __ldg(hu+1);
            float4* t = (float4*)((float*)g_imsg + (size_t)dst*DN + oBase);
            red_add_v4(t,   make_float4((h0.x+o8[0])*w,(h0.y+o8[1])*w,
                                        (h0.z+o8[2])*w,(h0.w+o8[3])*w));
            red_add_v4(t+1, make_float4((h1.x+o8[4])*w,(h1.y+o8[5])*w,
                                        (h1.z+o8[6])*w,(h1.w+o8[7])*w));
        } else {
            const float4* hi = (const float4*)((const float*)g_hi
                               + ((size_t)r*NII + dst)*DN + oBase);
            float4 h0 = __ldg(hi), h1 = __ldg(hi+1);
            float4* t = (float4*)((float*)g_umsg + (size_t)src*DN + oBase);
            red_add_v4(t,   make_float4((h0.x+o8[0])*w,(h0.y+o8[1])*w,
                                        (h0.z+o8[2])*w,(h0.w+o8[3])*w));
            red_add_v4(t+1, make_float4((h1.x+o8[4])*w,(h1.y+o8[5])*w,
                                        (h1.z+o8[6])*w,(h1.w+o8[7])*w));
        }
    }
}

// ---------------- K3: FC epilogue (4 nodes x 4 outputs/thread) + state restore --
// 16-thread group handles nodes {4b..4b+3}; after reading, restores zeros to the
// message accumulators and norm arrays so the next launch starts from zero state.
__global__ void __launch_bounds__(256) k_fc(
    const float* __restrict__ ufc_w, const float* __restrict__ ufc_b,
    const float* __restrict__ ifc_w, const float* __restrict__ ifc_b,
    float* __restrict__ out)
{
    __shared__ float Ws[DN*DOUT];   // transposed: Ws[j*64+o] = W[o*16+j]
    __shared__ float Bs[DOUT];
    int side = blockIdx.y;
    const float* W = side ? ifc_w : ufc_w;
    const float* B = side ? ifc_b : ufc_b;
    for (int i = threadIdx.x; i < DN*DOUT; i += 256){
        int o = i >> 4, j = i & 15;         // coalesced gmem read of W
        Ws[j*DOUT + o] = W[i];
    }
    if (threadIdx.x < DOUT) Bs[threadIdx.x] = B[threadIdx.x];
    __syncthreads();

    int idx = blockIdx.x*256 + threadIdx.x;   // < (NUU/4)*16 = 80000
    if (idx >= (NUU/4)*16) return;
    int b4 = idx >> 4;                        // node group: nodes 4b4..4b4+3
    int j  = idx & 15;
    int o4 = j*4;

    float4* msg4 = (float4*)(side ? g_imsg : g_umsg) + (size_t)b4*16;  // 16 float4s
    float4 bias = *(const float4*)(Bs + o4);
    float4 acc[4];
    #pragma unroll
    for (int pn=0;pn<4;pn++) acc[pn] = bias;

    #pragma unroll
    for (int q=0;q<4;q++){
        float4 mv[4];
        #pragma unroll
        for (int pn=0;pn<4;pn++) mv[pn] = msg4[pn*4 + q];   // broadcast within group
        #pragma unroll
        for (int t=0;t<4;t++){
            const float4 wv = *(const float4*)(Ws + (4*q+t)*DOUT + o4);  // reused x4
            #pragma unroll
            for (int pn=0;pn<4;pn++){
                float mcomp = (t==0)?mv[pn].x:(t==1)?mv[pn].y:(t==2)?mv[pn].z:mv[pn].w;
                float x = (mcomp > 0.f) ? mcomp : 0.1f*mcomp;
                acc[pn].x += x*wv.x;  acc[pn].y += x*wv.y;
                acc[pn].z += x*wv.z;  acc[pn].w += x*wv.w;
            }
        }
    }

    float* ob = out + (size_t)side*NUU*DOUT;
    #pragma unroll
    for (int pn=0;pn<4;pn++)
        *(float4*)(ob + (size_t)(4*b4+pn)*DOUT + o4) = acc[pn];

    // ---- restore zero state (reads above are complete in-registers) ----
    __syncwarp();
    float4 z = make_float4(0.f,0.f,0.f,0.f);
    msg4[j] = z;                                       // group zeroes its 256B chunk
    if (j == 0)
        *(float4*)((side ? g_norm_i : g_norm_u) + (size_t)b4*4) = z;
}

// ---------------- launch ----------------
extern "C" void kernel_launch(void* const* d_in, const int* in_sizes, int n_in,
                              void* d_out, int out_size)
{
    const float* user_h      = (const float*)d_in[0];
    const float* item_h      = (const float*)d_in[1];
    const float* user_hsum   = (const float*)d_in[2];
    const float* item_hsum   = (const float*)d_in[3];
    const float* review_feat = (const float*)d_in[4];
    const float* prototypes  = (const float*)d_in[5];
    const float* eta         = (const float*)d_in[6];
    const float* node_w_fwd  = (const float*)d_in[7];
    const float* review_w_fwd= (const float*)d_in[8];
    const float* node_w_rev  = (const float*)d_in[9];
    const float* review_w_rev= (const float*)d_in[10];
    const float* ufc_w       = (const float*)d_in[11];
    const float* ufc_b       = (const float*)d_in[12];
    const float* ifc_w       = (const float*)d_in[13];
    const float* ifc_b       = (const float*)d_in[14];
    const int*   edge_src    = (const int*)d_in[15];
    const int*   edge_dst    = (const int*)d_in[16];
    const int*   kp          = (const int*)d_in[17];
    float* out = (float*)d_out;

    k_fuse<<<dim3(BLEND_BX + 2*NODE_BX, R), 256>>>(
        user_h, item_h, user_hsum, item_hsum, review_feat, prototypes, eta,
        node_w_fwd, node_w_rev, edge_src, edge_dst, kp);
    k_msg <<<dim3((E+TILE_E-1)/TILE_E, R), 256>>>(
        review_feat, review_w_fwd, review_w_rev, edge_src, edge_dst, kp, out);
    k_fc  <<<dim3(((NUU/4)*16 + 255)/256, 2), 256>>>(
        ufc_w, ufc_b, ifc_w, ifc_b, out);
}